// round 14
// baseline (speedup 1.0000x reference)
#include <cuda_runtime.h>
#include <math.h>

constexpr int NNODE = 8192;
constexpr int NEDGE = 98304;
constexpr int EPB   = 32;

constexpr float SQRT3     = 1.7320508075688772f;
constexpr float INV_SQRT3 = 0.5773502691896258f;
constexpr float NORM24    = 0.20412414523193154f;  // 1/sqrt(24)
constexpr float INV_SQRT8 = 0.35355339059327373f;
constexpr float CEMB      = 1.14136f * 7.389056098930650f * 3.1622776601683795f;
constexpr float EMB_STEP  = 3.0f / 11.0f;
constexpr float INV_STEP  = 11.0f / 3.0f;

__device__ float g_qk0[NNODE * 16];
__device__ float g_qk1[NNODE * 24];
__device__ float g_z[NNODE];
__device__ float g_pot3[NNODE * 3];
__device__ float g_expv[NEDGE];
__device__ float g_cutw[NEDGE];
__device__ float g_sh1[NEDGE * 3];
__device__ float g_vflat[NEDGE * 40];
__device__ float g_wp[NEDGE * 72];

// B pre-packed in mma-fragment order: [path][(kk*72 + ntile)*32 + q*8 + g]
__device__ uint4 g_Bpk[2][4 * 72 * 32];

__device__ __forceinline__ float sus(float x) {
    return x > 0.f ? __expf(-1.f / x) : 0.f;
}

__device__ __forceinline__ unsigned f2tf(float x) {
    unsigned r;
    asm("cvt.rna.tf32.f32 %0, %1;" : "=r"(r) : "f"(x));
    return r;
}

__device__ __forceinline__ void mma1688(float* c, const unsigned* a, unsigned b0, unsigned b1) {
    asm("mma.sync.aligned.m16n8k8.row.col.f32.tf32.tf32.f32 "
        "{%0,%1,%2,%3},{%4,%5,%6,%7},{%8,%9},{%0,%1,%2,%3};"
        : "+f"(c[0]), "+f"(c[1]), "+f"(c[2]), "+f"(c[3])
        : "r"(a[0]), "r"(a[1]), "r"(a[2]), "r"(a[3]), "r"(b0), "r"(b1));
}

// ---------------- zero scratch + output ----------------
__global__ void kZero(float* __restrict__ out) {
    int i = blockIdx.x * blockDim.x + threadIdx.x;
    if (i < NNODE * 40) out[i] = 0.f;
    if (i < NNODE) g_z[i] = 0.f;
    if (i < NNODE * 3) g_pot3[i] = 0.f;
}

// ---------------- pack W2k/W2v into tf32 hi/lo mma fragments ----------------
__global__ void kPrep(const float* __restrict__ W2k, const float* __restrict__ W2v) {
    int i = blockIdx.x * blockDim.x + threadIdx.x;
    if (i >= 2 * 4 * 72 * 32) return;
    int path = i / (4 * 72 * 32);
    int r    = i % (4 * 72 * 32);
    int kk   = r / (72 * 32);
    int r2   = r % (72 * 32);
    int nt   = r2 / 32;
    int l    = r2 % 32;
    int q = l / 8, g = l % 8;
    const float* W2 = path ? W2v : W2k;
    int col = nt * 8 + g;
    float v0 = __ldg(&W2[(kk * 8 + q) * 576 + col]);
    float v1 = __ldg(&W2[(kk * 8 + q + 4) * 576 + col]);
    unsigned h0 = f2tf(v0), h1 = f2tf(v1);
    unsigned l0 = f2tf(v0 - __uint_as_float(h0));
    unsigned l1 = f2tf(v1 - __uint_as_float(h1));
    g_Bpk[path][(kk * 72 + nt) * 32 + l] = make_uint4(h0, l0, h1, l1);
}

// ---------------- per-node qk precompute ----------------
__global__ void kQK(const float* __restrict__ feats,
                    const float* __restrict__ Wq0, const float* __restrict__ Wq1,
                    const float* __restrict__ Wd00, const float* __restrict__ Wd11) {
    int nd = blockIdx.x * blockDim.x + threadIdx.x;
    if (nd >= NNODE) return;
    const float* f = &feats[(size_t)nd * 40];
    float q0[16];
#pragma unroll
    for (int o = 0; o < 16; o++) {
        float a = 0.f;
#pragma unroll
        for (int i = 0; i < 16; i++) a += f[i] * __ldg(&Wq0[i * 16 + o]);
        q0[o] = a * 0.25f;
    }
#pragma unroll
    for (int j = 0; j < 16; j++) {
        float a = 0.f;
#pragma unroll
        for (int i = 0; i < 16; i++) a += q0[i] * __ldg(&Wd00[i * 16 + j]);
        g_qk0[(size_t)nd * 16 + j] = a;
    }
    float q1[24];
#pragma unroll
    for (int o = 0; o < 8; o++)
#pragma unroll
        for (int d = 0; d < 3; d++) {
            float a = 0.f;
#pragma unroll
            for (int i = 0; i < 8; i++) a += f[16 + i * 3 + d] * __ldg(&Wq1[i * 8 + o]);
            q1[o * 3 + d] = a * INV_SQRT8;
        }
#pragma unroll
    for (int j = 0; j < 8; j++)
#pragma unroll
        for (int d = 0; d < 3; d++) {
            float a = 0.f;
#pragma unroll
            for (int i = 0; i < 8; i++) a += q1[i * 3 + d] * __ldg(&Wd11[i * 8 + j]);
            g_qk1[(size_t)nd * 24 + j * 3 + d] = a;
        }
}

// smem float offsets (EPB=32); s_w pitch 580 (16B-aligned rows for float4 reads)
constexpr int PITCHW = 580;
constexpr int PITCHH = 66;
constexpr int OFF_W    = 0;        // 32*580 = 18560
constexpr int OFF_HHI  = 18560;    // 2112
constexpr int OFF_HLO  = 20672;    // 2112
constexpr int OFF_HP   = 22784;    // 2048
constexpr int OFF_X0   = 24832;    // 32*24 (X0*NORM24 + x1s*INV_SQRT3*NORM24)
constexpr int OFF_X1   = 25600;    // 32*24 (x1*NORM24)
constexpr int OFF_QK0  = 26368;    // 32*16
constexpr int OFF_QK1T = 26880;    // 32*24, [e][d*8+o] = qk1[o,d]*INV_SQRT3
constexpr int OFF_EMB  = 27648;    // 32*10
constexpr int OFF_SH   = 27968;    // 32*3 raw sh
constexpr int OFF_SHN  = 28064;    // 32*3 sh*INV_SQRT3
constexpr int OFF_SHQK = 28160;    // 32*8
constexpr int OFF_CUT  = 28416;    // 32
constexpr int OFF_IDX  = 28448;    // 64 ints
constexpr int SMEM_FLOATS = 28512; // 114048 bytes

// 3xTF32 mma GEMM: D[32e,576] = H[32e,32c] @ W2[32c,576], one path.
__device__ __forceinline__ void gemm_mma(int path, const float* __restrict__ sHhi,
                                         const float* __restrict__ sHlo,
                                         float* __restrict__ s_w, int lane, int warp) {
    const uint4* __restrict__ B = g_Bpk[path];
    const int g = lane >> 2, q = lane & 3;
    const int chA = path * 32 + q;
    float acc[2][9][4];
#pragma unroll
    for (int t = 0; t < 2; t++)
#pragma unroll
        for (int n = 0; n < 9; n++) {
            acc[t][n][0] = 0.f; acc[t][n][1] = 0.f; acc[t][n][2] = 0.f; acc[t][n][3] = 0.f;
        }
#pragma unroll
    for (int kk = 0; kk < 4; kk++) {
        unsigned ah[2][4], al[2][4];
#pragma unroll
        for (int t = 0; t < 2; t++) {
            int ab = (16 * t + g) * PITCHH + chA + kk * 8;
            ah[t][0] = __float_as_uint(sHhi[ab]);
            ah[t][1] = __float_as_uint(sHhi[ab + 8 * PITCHH]);
            ah[t][2] = __float_as_uint(sHhi[ab + 4]);
            ah[t][3] = __float_as_uint(sHhi[ab + 8 * PITCHH + 4]);
            al[t][0] = __float_as_uint(sHlo[ab]);
            al[t][1] = __float_as_uint(sHlo[ab + 8 * PITCHH]);
            al[t][2] = __float_as_uint(sHlo[ab + 4]);
            al[t][3] = __float_as_uint(sHlo[ab + 8 * PITCHH + 4]);
        }
        const uint4* bp = B + (kk * 72 + warp * 9) * 32 + q * 8 + g;
#pragma unroll
        for (int n = 0; n < 9; n++) {
            uint4 b = __ldg(bp + n * 32);
#pragma unroll
            for (int t = 0; t < 2; t++) {
                mma1688(acc[t][n], ah[t], b.x, b.z);
                mma1688(acc[t][n], ah[t], b.y, b.w);
                mma1688(acc[t][n], al[t], b.x, b.z);
            }
        }
    }
#pragma unroll
    for (int t = 0; t < 2; t++)
#pragma unroll
        for (int n = 0; n < 9; n++) {
            int col = warp * 72 + 8 * n + 2 * q;
            *(float2*)&s_w[(16 * t + g) * PITCHW + col]     = make_float2(acc[t][n][0], acc[t][n][1]);
            *(float2*)&s_w[(16 * t + g + 8) * PITCHW + col] = make_float2(acc[t][n][2], acc[t][n][3]);
        }
}

__global__ void __launch_bounds__(256, 2)
kEdgeMain(const float* __restrict__ feats, const float* __restrict__ pos,
          const int* __restrict__ esrc, const int* __restrict__ edst,
          const float* __restrict__ W1k, const float* __restrict__ W1v,
          const float* __restrict__ W1p, const float* __restrict__ W2p) {
    extern __shared__ float sm[];
    float* s_w    = sm + OFF_W;
    float* s_Hhi  = sm + OFF_HHI;
    float* s_Hlo  = sm + OFF_HLO;
    float* s_Hp   = sm + OFF_HP;
    float* s_X0   = sm + OFF_X0;
    float* s_x1   = sm + OFF_X1;
    float* s_qk0  = sm + OFF_QK0;
    float* s_qk1t = sm + OFF_QK1T;
    float* s_emb  = sm + OFF_EMB;
    float* s_sh   = sm + OFF_SH;
    float* s_shn  = sm + OFF_SHN;
    float* s_shqk = sm + OFF_SHQK;
    float* s_cut  = sm + OFF_CUT;
    int*   s_src  = (int*)(sm + OFF_IDX);
    int*   s_dst  = (int*)(sm + OFF_IDX + 32);

    const int tid  = threadIdx.x;
    const int lane = tid & 31;
    const int warp = tid >> 5;
    const int e0   = blockIdx.x * EPB;

    // phase 1: per-edge scalars
    if (tid < EPB) {
        int e = e0 + tid;
        int s = esrc[e], d = edst[e];
        s_src[tid] = s; s_dst[tid] = d;
        float vx = pos[s * 3 + 0] - pos[d * 3 + 0];
        float vy = pos[s * 3 + 1] - pos[d * 3 + 1];
        float vz = pos[s * 3 + 2] - pos[d * 3 + 2];
        float elen = sqrtf(vx * vx + vy * vy + vz * vz + 1e-12f);
        float invl = SQRT3 / elen;
        float shx = vx * invl, shy = vy * invl, shz = vz * invl;
        s_sh[tid * 3 + 0] = shx; s_sh[tid * 3 + 1] = shy; s_sh[tid * 3 + 2] = shz;
        s_shn[tid * 3 + 0] = shx * INV_SQRT3;
        s_shn[tid * 3 + 1] = shy * INV_SQRT3;
        s_shn[tid * 3 + 2] = shz * INV_SQRT3;
        g_sh1[(size_t)e * 3 + 0] = shx; g_sh1[(size_t)e * 3 + 1] = shy; g_sh1[(size_t)e * 3 + 2] = shz;
        float cut = sus(10.f * (1.f - elen * (1.f / 3.f)));
        s_cut[tid] = cut;
        g_cutw[e] = cut;
#pragma unroll
        for (int b = 0; b < 10; b++) {
            float diff = (elen - EMB_STEP * (float)(b + 1)) * INV_STEP;
            s_emb[tid * 10 + b] = CEMB * sus(diff + 1.f) * sus(1.f - diff);
        }
    }
    __syncthreads();

    // phase 2: gather node data (X0/x1 prescaled by NORM24; qk1 transposed*INV_SQRT3)
    for (int idx = tid; idx < 32 * 16; idx += 256) {
        int e = idx >> 4, i = idx & 15;
        s_X0[e * 24 + i]  = feats[(size_t)s_src[e] * 40 + i] * NORM24;
        s_qk0[e * 16 + i] = g_qk0[(size_t)s_dst[e] * 16 + i];
    }
    for (int idx = tid; idx < 32 * 24; idx += 256) {
        int e = idx / 24, r = idx % 24;
        s_x1[e * 24 + r] = feats[(size_t)s_src[e] * 40 + 16 + r] * NORM24;
        int d = r >> 3, o = r & 7;
        s_qk1t[e * 24 + r] = g_qk1[(size_t)s_dst[e] * 24 + o * 3 + d] * INV_SQRT3;
    }
    __syncthreads();

    // phase 3a: x1s (scaled) and shqk
    {
        int e = tid >> 3, i = tid & 7;
        const float* xp = &s_x1[e * 24 + i * 3];   // already *NORM24
        s_X0[e * 24 + 16 + i] =
            (xp[0] * s_sh[e * 3] + xp[1] * s_sh[e * 3 + 1] + xp[2] * s_sh[e * 3 + 2]) * INV_SQRT3;
        // shqk[e][o] = sum_d shn[d] * qk1t[d][o]
        int o = i;
        s_shqk[e * 8 + o] = s_shn[e * 3 + 0] * s_qk1t[e * 24 + 0 * 8 + o]
                          + s_shn[e * 3 + 1] * s_qk1t[e * 24 + 1 * 8 + o]
                          + s_shn[e * 3 + 2] * s_qk1t[e * 24 + 2 * 8 + o];
    }
    // phase 3b: H = silu(emb @ W1); k/v channels split to tf32 hi/lo, p kept f32
#pragma unroll 1
    for (int r = 0; r < 16; r++) {
        int id = r * 256 + tid;
        int e = id & 31, ch = id >> 5;
        const float* W1; int cc, ld;
        if (ch < 32)      { W1 = W1k; cc = ch;      ld = 32; }
        else if (ch < 64) { W1 = W1v; cc = ch - 32; ld = 32; }
        else              { W1 = W1p; cc = ch - 64; ld = 64; }
        float a = 0.f;
#pragma unroll
        for (int b = 0; b < 10; b++) a += s_emb[e * 10 + b] * __ldg(&W1[b * ld + cc]);
        a = a / (1.f + __expf(-a));
        if (ch < 64) {
            unsigned hi = f2tf(a);
            s_Hhi[e * PITCHH + ch] = __uint_as_float(hi);
            s_Hlo[e * PITCHH + ch] = __uint_as_float(f2tf(a - __uint_as_float(hi)));
        } else {
            s_Hp[e * 64 + (ch - 64)] = a;
        }
    }
    __syncthreads();

    const int ebase = warp * 4;

    // ===== K path =====
    gemm_mma(0, s_Hhi, s_Hlo, s_w, lane, warp);
    __syncthreads();
#pragma unroll 1
    for (int s4 = 0; s4 < 4; s4++) {
        int e = ebase + s4;
        const float* w   = s_w + e * PITCHW;
        const float* X0n = s_X0 + e * 24;
        float part = 0.f;
#pragma unroll
        for (int m = 0; m < 3; m++) {          // cols 0..383 (x0 + x1s regions)
            int c = lane + 32 * m;
            float4 w4 = *(const float4*)(w + 4 * c);
            float4 q4 = *(const float4*)(s_qk0 + e * 16 + (c & 3) * 4);
            part += X0n[c >> 2] * (w4.x * q4.x + w4.y * q4.y + w4.z * q4.z + w4.w * q4.w);
        }
        {   // cols 384..511 (w01 via shqk)
            float4 w4 = *(const float4*)(w + 384 + 4 * lane);
            float4 q4 = *(const float4*)(s_shqk + e * 8 + (lane & 1) * 4);
            part += X0n[lane >> 1] * (w4.x * q4.x + w4.y * q4.y + w4.z * q4.z + w4.w * q4.w);
        }
        if (lane < 16) {   // cols 512..575 (w10 via qk1t)
            float4 w4 = *(const float4*)(w + 512 + 4 * lane);
            int i = lane >> 1, o4 = (lane & 1) * 4;
            const float* x1n = s_x1 + e * 24 + i * 3;
            const float* qt  = s_qk1t + e * 24;
            float4 y = make_float4(0.f, 0.f, 0.f, 0.f);
#pragma unroll
            for (int d = 0; d < 3; d++) {
                float4 qq = *(const float4*)(qt + d * 8 + o4);
                float xv = x1n[d];
                y.x += xv * qq.x; y.y += xv * qq.y; y.z += xv * qq.z; y.w += xv * qq.w;
            }
            part += w4.x * y.x + w4.y * y.y + w4.z * y.z + w4.w * y.w;
        }
#pragma unroll
        for (int off = 16; off; off >>= 1)
            part += __shfl_xor_sync(0xffffffffu, part, off);
        if (lane == 0) {
            float dot = part * NORM24;
            float ev = s_cut[e] * expf(dot);
            g_expv[e0 + e] = ev;
            atomicAdd(&g_z[s_dst[e]], ev);
        }
    }
    __syncthreads();

    // ===== V path =====
    gemm_mma(1, s_Hhi, s_Hlo, s_w, lane, warp);
    __syncthreads();
#pragma unroll 1
    for (int s4 = 0; s4 < 4; s4++) {
        int e = ebase + s4;
        const float* w   = s_w + e * PITCHW;
        const float* X0n = s_X0 + e * 24;
        float* vf = &g_vflat[(size_t)(e0 + e) * 40];
        // out0: lanes (h = lane>>4 half of i, o = lane&15)
        {
            int o = lane & 15, h = lane >> 4;
            float p0 = 0.f;
#pragma unroll
            for (int t = 0; t < 12; t++) {
                int i = 12 * h + t;
                p0 += X0n[i] * w[i * 16 + o];
            }
            p0 += __shfl_xor_sync(0xffffffffu, p0, 16);
            if (lane < 16) vf[o] = p0;
        }
        // xw[o8] over 4 i-groups
        int o8 = lane & 7, grp = lane >> 3;
        float xw = 0.f;
#pragma unroll
        for (int t = 0; t < 4; t++) {
            int i = grp + 4 * t;
            xw += X0n[i] * w[384 + i * 8 + o8];
        }
        xw += __shfl_xor_sync(0xffffffffu, xw, 8);
        xw += __shfl_xor_sync(0xffffffffu, xw, 16);   // every lane: xw for its o8
        // out1: lanes 0..23 as (o,d) = (lane/3, lane%3)
        int oo = lane / 3;
        int dd = lane - 3 * oo;
        int ooc = (oo < 8) ? oo : 7;
        float xwo = __shfl_sync(0xffffffffu, xw, ooc);
        float p1 = 0.f;
#pragma unroll
        for (int i = 0; i < 8; i++)
            p1 += s_x1[e * 24 + i * 3 + dd] * w[512 + i * 8 + ooc];
        if (lane < 24) vf[16 + lane] = p1 + xwo * s_shn[e * 3 + dd];
    }
    __syncthreads();

    // ===== P path: only 72 of 1152 W2p columns are live =====
    for (int idx = tid; idx < 64 * 72; idx += 256) {
        int c = idx / 72, j = idx % 72;
        int jj   = (j < 48) ? j : j - 48;
        int base = (j < 48) ? 0 : 512;
        int col  = base + (jj / 3) * 32 + (jj % 3);
        s_w[c * 72 + j] = __ldg(&W2p[c * 1152 + col]);
    }
    __syncthreads();
    {
        float pa0[4] = {0, 0, 0, 0}, pa1[4] = {0, 0, 0, 0}, pa2[4] = {0, 0, 0, 0};
#pragma unroll 2
        for (int c = 0; c < 64; c++) {
            float w0 = s_w[c * 72 + lane];
            float w1 = s_w[c * 72 + 32 + lane];
            float w2 = (lane < 8) ? s_w[c * 72 + 64 + lane] : 0.f;
#pragma unroll
            for (int s4 = 0; s4 < 4; s4++) {
                float h = s_Hp[(ebase + s4) * 64 + c];
                pa0[s4] += h * w0; pa1[s4] += h * w1; pa2[s4] += h * w2;
            }
        }
#pragma unroll
        for (int s4 = 0; s4 < 4; s4++) {
            size_t e = (size_t)(e0 + ebase + s4);
            g_wp[e * 72 + lane]      = pa0[s4];
            g_wp[e * 72 + 32 + lane] = pa1[s4];
            if (lane < 8) g_wp[e * 72 + 64 + lane] = pa2[s4];
        }
    }
}

// ---------------- softmax + scatter att ----------------
__global__ void kAttScatter(const int* __restrict__ edst, float* __restrict__ out) {
    int idx = blockIdx.x * blockDim.x + threadIdx.x;
    if (idx >= NEDGE * 40) return;
    int e = idx / 40, j = idx - e * 40;
    int d = edst[e];
    float z = g_z[d];
    float zz = (z == 0.f) ? 1.f : z;
    float alpha = g_expv[e] / zz;
    float coef = (alpha > 0.f) ? sqrtf(alpha) : 0.f;
    if (coef != 0.f)
        atomicAdd(&out[(size_t)d * 40 + j], coef * g_vflat[(size_t)e * 40 + j]);
}

// ---------------- p pass (only p0 cols 0..2 are live) ----------------
__global__ void kPEdge(const int* __restrict__ esrc, const int* __restrict__ edst,
                       const float* __restrict__ att) {
    int e = blockIdx.x * blockDim.x + threadIdx.x;
    if (e >= NEDGE) return;
    int s = esrc[e], d = edst[e];
    const float* a  = &att[(size_t)s * 40];
    const float* wp = &g_wp[(size_t)e * 72];
    float shx = g_sh1[(size_t)e * 3 + 0];
    float shy = g_sh1[(size_t)e * 3 + 1];
    float shz = g_sh1[(size_t)e * 3 + 2];
    float p0 = 0.f, p1 = 0.f, p2 = 0.f;
#pragma unroll
    for (int i = 0; i < 16; i++) {
        float ai = a[i];
        p0 += ai * wp[i * 3 + 0];
        p1 += ai * wp[i * 3 + 1];
        p2 += ai * wp[i * 3 + 2];
    }
#pragma unroll
    for (int i = 0; i < 8; i++) {
        float as = (a[16 + i * 3] * shx + a[16 + i * 3 + 1] * shy + a[16 + i * 3 + 2] * shz) * INV_SQRT3;
        p0 += as * wp[48 + i * 3 + 0];
        p1 += as * wp[48 + i * 3 + 1];
        p2 += as * wp[48 + i * 3 + 2];
    }
    float cw = g_cutw[e] * NORM24;
    atomicAdd(&g_pot3[(size_t)d * 3 + 0], cw * p0);
    atomicAdd(&g_pot3[(size_t)d * 3 + 1], cw * p1);
    atomicAdd(&g_pot3[(size_t)d * 3 + 2], cw * p2);
}

// ---------------- curl fixup ----------------
__global__ void kCurl(float* __restrict__ out) {
    int n = blockIdx.x * blockDim.x + threadIdx.x;
    if (n >= NNODE) return;
    float p0 = g_pot3[(size_t)n * 3 + 0];
    float p1 = g_pot3[(size_t)n * 3 + 1];
    float p2 = g_pot3[(size_t)n * 3 + 2];
    out[(size_t)n * 40 + 0] += 0.1f * (p2 - p1);
    out[(size_t)n * 40 + 1] += 0.1f * (p0 - p2);
    out[(size_t)n * 40 + 2] += 0.1f * (p1 - p0);
}

extern "C" void kernel_launch(void* const* d_in, const int* in_sizes, int n_in,
                              void* d_out, int out_size) {
    const float* feats = (const float*)d_in[0];
    const float* pos   = (const float*)d_in[1];
    const int*   esrc  = (const int*)d_in[2];
    const int*   edst  = (const int*)d_in[3];
    const float* Wq0   = (const float*)d_in[4];
    const float* Wq1   = (const float*)d_in[5];
    const float* W1k   = (const float*)d_in[6];
    const float* W2k   = (const float*)d_in[7];
    const float* W1v   = (const float*)d_in[8];
    const float* W2v   = (const float*)d_in[9];
    const float* Wd00  = (const float*)d_in[10];
    const float* Wd11  = (const float*)d_in[11];
    const float* W1p   = (const float*)d_in[12];
    const float* W2p   = (const float*)d_in[13];
    float* out = (float*)d_out;

    const int smem_bytes = SMEM_FLOATS * 4;
    cudaFuncSetAttribute(kEdgeMain, cudaFuncAttributeMaxDynamicSharedMemorySize, smem_bytes);

    kZero<<<(NNODE * 40 + 255) / 256, 256>>>(out);
    kPrep<<<(2 * 4 * 72 * 32 + 255) / 256, 256>>>(W2k, W2v);
    kQK<<<(NNODE + 255) / 256, 256>>>(feats, Wq0, Wq1, Wd00, Wd11);
    kEdgeMain<<<NEDGE / EPB, 256, smem_bytes>>>(feats, pos, esrc, edst,
                                                W1k, W1v, W1p, W2p);
    kAttScatter<<<(NEDGE * 40 + 255) / 256, 256>>>(edst, out);
    kPEdge<<<(NEDGE + 255) / 256, 256>>>(esrc, edst, out);
    kCurl<<<(NNODE + 255) / 256, 256>>>(out);
}

// round 17
// speedup vs baseline: 1.4146x; 1.4146x over previous
#include <cuda_runtime.h>
#include <math.h>

constexpr int NNODE = 8192;
constexpr int NEDGE = 98304;
constexpr int EPB   = 32;

constexpr float SQRT3     = 1.7320508075688772f;
constexpr float INV_SQRT3 = 0.5773502691896258f;
constexpr float NORM24    = 0.20412414523193154f;  // 1/sqrt(24)
constexpr float INV_SQRT8 = 0.35355339059327373f;
constexpr float CEMB      = 1.14136f * 7.389056098930650f * 3.1622776601683795f;
constexpr float EMB_STEP  = 3.0f / 11.0f;
constexpr float INV_STEP  = 11.0f / 3.0f;

__device__ float g_qk0[NNODE * 16];
__device__ float g_qk1[NNODE * 24];
__device__ float g_z[NNODE];
__device__ float g_pot3[NNODE * 3];
__device__ float g_expv[NEDGE];
__device__ float g_cutw[NEDGE];
__device__ float g_sh1[NEDGE * 3];
__device__ float g_vflat[NEDGE * 40];
__device__ float g_wp[NEDGE * 72];

// B pre-packed in mma-fragment order: [path][(kk*72 + ntile)*32 + q*8 + g]
// uint4 = (hi @ k=kk*8+q, lo @ k=kk*8+q, hi @ k=kk*8+q+4, lo @ k=kk*8+q+4), col = ntile*8+g
__device__ uint4 g_Bpk[2][4 * 72 * 32];

__device__ __forceinline__ float sus(float x) {
    return x > 0.f ? __expf(-1.f / x) : 0.f;
}

__device__ __forceinline__ unsigned f2tf(float x) {
    unsigned r;
    asm("cvt.rna.tf32.f32 %0, %1;" : "=r"(r) : "f"(x));
    return r;
}

__device__ __forceinline__ void mma1688(float* c, const unsigned* a, unsigned b0, unsigned b1) {
    asm("mma.sync.aligned.m16n8k8.row.col.f32.tf32.tf32.f32 "
        "{%0,%1,%2,%3},{%4,%5,%6,%7},{%8,%9},{%0,%1,%2,%3};"
        : "+f"(c[0]), "+f"(c[1]), "+f"(c[2]), "+f"(c[3])
        : "r"(a[0]), "r"(a[1]), "r"(a[2]), "r"(a[3]), "r"(b0), "r"(b1));
}

// ---------------- fused init: zero + W2 fragment pack + per-node qk ----------------
__global__ void kInit(float* __restrict__ out,
                      const float* __restrict__ W2k, const float* __restrict__ W2v,
                      const float* __restrict__ feats,
                      const float* __restrict__ Wq0, const float* __restrict__ Wq1,
                      const float* __restrict__ Wd00, const float* __restrict__ Wd11) {
    int i = blockIdx.x * blockDim.x + threadIdx.x;
    if (i < NNODE * 40) out[i] = 0.f;
    if (i < NNODE) g_z[i] = 0.f;
    if (i < NNODE * 3) g_pot3[i] = 0.f;

    // ---- W2 fragment packing ----
    if (i < 2 * 4 * 72 * 32) {
        int path = i / (4 * 72 * 32);
        int r    = i % (4 * 72 * 32);
        int kk   = r / (72 * 32);
        int r2   = r % (72 * 32);
        int nt   = r2 / 32;
        int l    = r2 % 32;
        int q = l / 8, g = l % 8;
        const float* W2 = path ? W2v : W2k;
        int col = nt * 8 + g;
        float v0 = __ldg(&W2[(kk * 8 + q) * 576 + col]);
        float v1 = __ldg(&W2[(kk * 8 + q + 4) * 576 + col]);
        unsigned h0 = f2tf(v0), h1 = f2tf(v1);
        unsigned l0 = f2tf(v0 - __uint_as_float(h0));
        unsigned l1 = f2tf(v1 - __uint_as_float(h1));
        g_Bpk[path][(kk * 72 + nt) * 32 + l] = make_uint4(h0, l0, h1, l1);
    }

    // ---- per-node qk precompute ----
    if (i < NNODE) {
        int nd = i;
        const float* f = &feats[(size_t)nd * 40];
        float q0[16];
#pragma unroll
        for (int o = 0; o < 16; o++) {
            float a = 0.f;
#pragma unroll
            for (int k = 0; k < 16; k++) a += f[k] * __ldg(&Wq0[k * 16 + o]);
            q0[o] = a * 0.25f;
        }
#pragma unroll
        for (int j = 0; j < 16; j++) {
            float a = 0.f;
#pragma unroll
            for (int k = 0; k < 16; k++) a += q0[k] * __ldg(&Wd00[k * 16 + j]);
            g_qk0[(size_t)nd * 16 + j] = a;
        }
        float q1[24];
#pragma unroll
        for (int o = 0; o < 8; o++)
#pragma unroll
            for (int d = 0; d < 3; d++) {
                float a = 0.f;
#pragma unroll
                for (int k = 0; k < 8; k++) a += f[16 + k * 3 + d] * __ldg(&Wq1[k * 8 + o]);
                q1[o * 3 + d] = a * INV_SQRT8;
            }
#pragma unroll
        for (int j = 0; j < 8; j++)
#pragma unroll
            for (int d = 0; d < 3; d++) {
                float a = 0.f;
#pragma unroll
                for (int k = 0; k < 8; k++) a += q1[k * 3 + d] * __ldg(&Wd11[k * 8 + j]);
                g_qk1[(size_t)nd * 24 + j * 3 + d] = a;
            }
    }
}

// smem float offsets (EPB=32); s_w pitch 578, H hi/lo pitch 66
constexpr int PITCHW = 578;
constexpr int PITCHH = 66;
constexpr int OFF_W   = 0;        // 32*578 = 18496
constexpr int OFF_HHI = 18496;    // 32*66 = 2112
constexpr int OFF_HLO = 20608;    // 2112
constexpr int OFF_HP  = 22720;    // 32*64 = 2048
constexpr int OFF_X0  = 24768;    // 32*24
constexpr int OFF_X1  = 25536;    // 32*24
constexpr int OFF_QK0 = 26304;    // 32*16
constexpr int OFF_QK1 = 26816;    // 32*24
constexpr int OFF_EMB = 27584;    // 32*10
constexpr int OFF_SH  = 27904;    // 32*3
constexpr int OFF_CUT = 28000;    // 32
constexpr int OFF_IDX = 28032;    // 64 ints
constexpr int SMEM_FLOATS = 28096; // 112384 bytes

// 3xTF32 mma GEMM: D[32e,576] = H[32e,32c] @ W2[32c,576], one path (k or v).
// Warp w owns cols [72w, 72w+72) as 9 n8 tiles; m split in 2 m16 tiles.
// B comes pre-packed per-lane: one LDG.128 per (kk, n-tile) feeds all 3
// compensation MMAs for BOTH m-tiles.
__device__ __forceinline__ void gemm_mma(int path, const float* __restrict__ sHhi,
                                         const float* __restrict__ sHlo,
                                         float* __restrict__ s_w, int lane, int warp) {
    const uint4* __restrict__ B = g_Bpk[path];
    const int g = lane >> 2, q = lane & 3;
    const int chA = path * 32 + q;
    float acc[2][9][4];
#pragma unroll
    for (int t = 0; t < 2; t++)
#pragma unroll
        for (int n = 0; n < 9; n++) {
            acc[t][n][0] = 0.f; acc[t][n][1] = 0.f; acc[t][n][2] = 0.f; acc[t][n][3] = 0.f;
        }
#pragma unroll
    for (int kk = 0; kk < 4; kk++) {
        unsigned ah[2][4], al[2][4];
#pragma unroll
        for (int t = 0; t < 2; t++) {
            int ab = (16 * t + g) * PITCHH + chA + kk * 8;
            ah[t][0] = __float_as_uint(sHhi[ab]);
            ah[t][1] = __float_as_uint(sHhi[ab + 8 * PITCHH]);
            ah[t][2] = __float_as_uint(sHhi[ab + 4]);
            ah[t][3] = __float_as_uint(sHhi[ab + 8 * PITCHH + 4]);
            al[t][0] = __float_as_uint(sHlo[ab]);
            al[t][1] = __float_as_uint(sHlo[ab + 8 * PITCHH]);
            al[t][2] = __float_as_uint(sHlo[ab + 4]);
            al[t][3] = __float_as_uint(sHlo[ab + 8 * PITCHH + 4]);
        }
        const uint4* bp = B + (kk * 72 + warp * 9) * 32 + q * 8 + g;
#pragma unroll
        for (int n = 0; n < 9; n++) {
            uint4 b = __ldg(bp + n * 32);
#pragma unroll
            for (int t = 0; t < 2; t++) {
                mma1688(acc[t][n], ah[t], b.x, b.z);   // hi*hi
                mma1688(acc[t][n], ah[t], b.y, b.w);   // hi*lo
                mma1688(acc[t][n], al[t], b.x, b.z);   // lo*hi
            }
        }
    }
#pragma unroll
    for (int t = 0; t < 2; t++)
#pragma unroll
        for (int n = 0; n < 9; n++) {
            int col = warp * 72 + 8 * n + 2 * q;
            *(float2*)&s_w[(16 * t + g) * PITCHW + col]     = make_float2(acc[t][n][0], acc[t][n][1]);
            *(float2*)&s_w[(16 * t + g + 8) * PITCHW + col] = make_float2(acc[t][n][2], acc[t][n][3]);
        }
}

__global__ void __launch_bounds__(256, 2)
kEdgeMain(const float* __restrict__ feats, const float* __restrict__ pos,
          const int* __restrict__ esrc, const int* __restrict__ edst,
          const float* __restrict__ W1k, const float* __restrict__ W1v,
          const float* __restrict__ W1p, const float* __restrict__ W2p) {
    extern __shared__ float sm[];
    float* s_w   = sm + OFF_W;
    float* s_Hhi = sm + OFF_HHI;
    float* s_Hlo = sm + OFF_HLO;
    float* s_Hp  = sm + OFF_HP;
    float* s_X0  = sm + OFF_X0;
    float* s_x1  = sm + OFF_X1;
    float* s_qk0 = sm + OFF_QK0;
    float* s_qk1 = sm + OFF_QK1;
    float* s_emb = sm + OFF_EMB;
    float* s_sh  = sm + OFF_SH;
    float* s_cut = sm + OFF_CUT;
    int*   s_src = (int*)(sm + OFF_IDX);
    int*   s_dst = (int*)(sm + OFF_IDX + 32);

    const int tid  = threadIdx.x;
    const int lane = tid & 31;
    const int warp = tid >> 5;
    const int e0   = blockIdx.x * EPB;

    // phase 1: per-edge scalars
    if (tid < EPB) {
        int e = e0 + tid;
        int s = esrc[e], d = edst[e];
        s_src[tid] = s; s_dst[tid] = d;
        float vx = pos[s * 3 + 0] - pos[d * 3 + 0];
        float vy = pos[s * 3 + 1] - pos[d * 3 + 1];
        float vz = pos[s * 3 + 2] - pos[d * 3 + 2];
        float elen = sqrtf(vx * vx + vy * vy + vz * vz + 1e-12f);
        float invl = SQRT3 / elen;
        float shx = vx * invl, shy = vy * invl, shz = vz * invl;
        s_sh[tid * 3 + 0] = shx; s_sh[tid * 3 + 1] = shy; s_sh[tid * 3 + 2] = shz;
        g_sh1[(size_t)e * 3 + 0] = shx; g_sh1[(size_t)e * 3 + 1] = shy; g_sh1[(size_t)e * 3 + 2] = shz;
        float cut = sus(10.f * (1.f - elen * (1.f / 3.f)));
        s_cut[tid] = cut;
        g_cutw[e] = cut;
#pragma unroll
        for (int b = 0; b < 10; b++) {
            float diff = (elen - EMB_STEP * (float)(b + 1)) * INV_STEP;
            s_emb[tid * 10 + b] = CEMB * sus(diff + 1.f) * sus(1.f - diff);
        }
    }
    __syncthreads();

    // phase 2: gather node data
    for (int idx = tid; idx < 32 * 16; idx += 256) {
        int e = idx >> 4, i = idx & 15;
        s_X0[e * 24 + i]  = feats[(size_t)s_src[e] * 40 + i];
        s_qk0[e * 16 + i] = g_qk0[(size_t)s_dst[e] * 16 + i];
    }
    for (int idx = tid; idx < 32 * 24; idx += 256) {
        int e = idx / 24, i = idx % 24;
        s_x1[e * 24 + i]  = feats[(size_t)s_src[e] * 40 + 16 + i];
        s_qk1[e * 24 + i] = g_qk1[(size_t)s_dst[e] * 24 + i];
    }
    __syncthreads();

    // phase 3a: x1s = (x1 . sh)/sqrt3
    {
        int e = tid >> 3, i = tid & 7;
        const float* xp = &s_x1[e * 24 + i * 3];
        s_X0[e * 24 + 16 + i] =
            (xp[0] * s_sh[e * 3] + xp[1] * s_sh[e * 3 + 1] + xp[2] * s_sh[e * 3 + 2]) * INV_SQRT3;
    }
    // phase 3b: H = silu(emb @ W1); k/v channels split to tf32 hi/lo, p kept f32
#pragma unroll 1
    for (int r = 0; r < 16; r++) {
        int id = r * 256 + tid;
        int e = id & 31, ch = id >> 5;
        const float* W1; int cc, ld;
        if (ch < 32)      { W1 = W1k; cc = ch;      ld = 32; }
        else if (ch < 64) { W1 = W1v; cc = ch - 32; ld = 32; }
        else              { W1 = W1p; cc = ch - 64; ld = 64; }
        float a = 0.f;
#pragma unroll
        for (int b = 0; b < 10; b++) a += s_emb[e * 10 + b] * __ldg(&W1[b * ld + cc]);
        a = a / (1.f + __expf(-a));
        if (ch < 64) {
            unsigned hi = f2tf(a);
            s_Hhi[e * PITCHH + ch] = __uint_as_float(hi);
            s_Hlo[e * PITCHH + ch] = __uint_as_float(f2tf(a - __uint_as_float(hi)));
        } else {
            s_Hp[e * 64 + (ch - 64)] = a;
        }
    }
    __syncthreads();

    const int ebase = warp * 4;

    // ===== K path =====
    gemm_mma(0, s_Hhi, s_Hlo, s_w, lane, warp);
    __syncthreads();
#pragma unroll 1
    for (int s4 = 0; s4 < 4; s4++) {
        int e = ebase + s4;
        const float* w  = s_w + e * PITCHW;
        const float* X0 = s_X0 + e * 24;
        float partial = 0.f;
        if (lane < 16) {
            int o = lane;
            float k0 = 0.f;
#pragma unroll
            for (int i = 0; i < 16; i++) k0 += X0[i] * w[i * 16 + o];
#pragma unroll
            for (int i = 0; i < 8; i++)  k0 += X0[16 + i] * w[256 + i * 16 + o];
            partial = k0 * NORM24 * s_qk0[e * 16 + o];
        } else if (lane < 24) {
            int o = lane - 16;
            float xw = 0.f;
#pragma unroll
            for (int i = 0; i < 16; i++) xw += X0[i] * w[384 + i * 8 + o];
            float t = 0.f;
#pragma unroll
            for (int d = 0; d < 3; d++) {
                float k1 = 0.f;
#pragma unroll
                for (int i = 0; i < 8; i++) k1 += s_x1[e * 24 + i * 3 + d] * w[512 + i * 8 + o];
                k1 = (xw * s_sh[e * 3 + d] * INV_SQRT3 + k1) * NORM24;
                t += k1 * s_qk1[e * 24 + o * 3 + d];
            }
            partial = t * INV_SQRT3;
        }
#pragma unroll
        for (int off = 16; off; off >>= 1)
            partial += __shfl_xor_sync(0xffffffffu, partial, off);
        if (lane == 0) {
            float dot = partial * NORM24;
            float ev = s_cut[e] * expf(dot);
            g_expv[e0 + e] = ev;
            atomicAdd(&g_z[s_dst[e]], ev);
        }
    }
    __syncthreads();

    // ===== V path =====
    gemm_mma(1, s_Hhi, s_Hlo, s_w, lane, warp);
    __syncthreads();
#pragma unroll 1
    for (int s4 = 0; s4 < 4; s4++) {
        int e = ebase + s4;
        const float* w  = s_w + e * PITCHW;
        const float* X0 = s_X0 + e * 24;
        float* vf = &g_vflat[(size_t)(e0 + e) * 40];
        if (lane < 16) {
            int o = lane;
            float v0 = 0.f;
#pragma unroll
            for (int i = 0; i < 16; i++) v0 += X0[i] * w[i * 16 + o];
#pragma unroll
            for (int i = 0; i < 8; i++)  v0 += X0[16 + i] * w[256 + i * 16 + o];
            vf[o] = v0 * NORM24;
        } else if (lane < 24) {
            int o = lane - 16;
            float xw = 0.f;
#pragma unroll
            for (int i = 0; i < 16; i++) xw += X0[i] * w[384 + i * 8 + o];
#pragma unroll
            for (int d = 0; d < 3; d++) {
                float v1 = 0.f;
#pragma unroll
                for (int i = 0; i < 8; i++) v1 += s_x1[e * 24 + i * 3 + d] * w[512 + i * 8 + o];
                v1 = (xw * s_sh[e * 3 + d] * INV_SQRT3 + v1) * NORM24;
                vf[16 + o * 3 + d] = v1;
            }
        }
    }
    __syncthreads();

    // ===== P path: only 72 of 1152 W2p columns are live =====
    for (int idx = tid; idx < 64 * 72; idx += 256) {
        int c = idx / 72, j = idx % 72;
        int jj   = (j < 48) ? j : j - 48;
        int base = (j < 48) ? 0 : 512;
        int col  = base + (jj / 3) * 32 + (jj % 3);
        s_w[c * 72 + j] = __ldg(&W2p[c * 1152 + col]);
    }
    __syncthreads();
    {
        float pa0[4] = {0, 0, 0, 0}, pa1[4] = {0, 0, 0, 0}, pa2[4] = {0, 0, 0, 0};
#pragma unroll 2
        for (int c = 0; c < 64; c++) {
            float w0 = s_w[c * 72 + lane];
            float w1 = s_w[c * 72 + 32 + lane];
            float w2 = (lane < 8) ? s_w[c * 72 + 64 + lane] : 0.f;
#pragma unroll
            for (int s4 = 0; s4 < 4; s4++) {
                float h = s_Hp[(ebase + s4) * 64 + c];
                pa0[s4] += h * w0; pa1[s4] += h * w1; pa2[s4] += h * w2;
            }
        }
#pragma unroll
        for (int s4 = 0; s4 < 4; s4++) {
            size_t e = (size_t)(e0 + ebase + s4);
            g_wp[e * 72 + lane]      = pa0[s4];
            g_wp[e * 72 + 32 + lane] = pa1[s4];
            if (lane < 8) g_wp[e * 72 + 64 + lane] = pa2[s4];
        }
    }
}

// ---------------- softmax + scatter att ----------------
__global__ void kAttScatter(const int* __restrict__ edst, float* __restrict__ out) {
    int idx = blockIdx.x * blockDim.x + threadIdx.x;
    if (idx >= NEDGE * 40) return;
    int e = idx / 40, j = idx - e * 40;
    int d = edst[e];
    float z = g_z[d];
    float zz = (z == 0.f) ? 1.f : z;
    float alpha = g_expv[e] / zz;
    float coef = (alpha > 0.f) ? sqrtf(alpha) : 0.f;
    if (coef != 0.f)
        atomicAdd(&out[(size_t)d * 40 + j], coef * g_vflat[(size_t)e * 40 + j]);
}

// ---------------- p pass (only p0 cols 0..2 are live) ----------------
__global__ void kPEdge(const int* __restrict__ esrc, const int* __restrict__ edst,
                       const float* __restrict__ att) {
    int e = blockIdx.x * blockDim.x + threadIdx.x;
    if (e >= NEDGE) return;
    int s = esrc[e], d = edst[e];
    const float* a  = &att[(size_t)s * 40];
    const float* wp = &g_wp[(size_t)e * 72];
    float shx = g_sh1[(size_t)e * 3 + 0];
    float shy = g_sh1[(size_t)e * 3 + 1];
    float shz = g_sh1[(size_t)e * 3 + 2];
    float p0 = 0.f, p1 = 0.f, p2 = 0.f;
#pragma unroll
    for (int i = 0; i < 16; i++) {
        float ai = a[i];
        p0 += ai * wp[i * 3 + 0];
        p1 += ai * wp[i * 3 + 1];
        p2 += ai * wp[i * 3 + 2];
    }
#pragma unroll
    for (int i = 0; i < 8; i++) {
        float as = (a[16 + i * 3] * shx + a[16 + i * 3 + 1] * shy + a[16 + i * 3 + 2] * shz) * INV_SQRT3;
        p0 += as * wp[48 + i * 3 + 0];
        p1 += as * wp[48 + i * 3 + 1];
        p2 += as * wp[48 + i * 3 + 2];
    }
    float cw = g_cutw[e] * NORM24;
    atomicAdd(&g_pot3[(size_t)d * 3 + 0], cw * p0);
    atomicAdd(&g_pot3[(size_t)d * 3 + 1], cw * p1);
    atomicAdd(&g_pot3[(size_t)d * 3 + 2], cw * p2);
}

// ---------------- curl fixup ----------------
__global__ void kCurl(float* __restrict__ out) {
    int n = blockIdx.x * blockDim.x + threadIdx.x;
    if (n >= NNODE) return;
    float p0 = g_pot3[(size_t)n * 3 + 0];
    float p1 = g_pot3[(size_t)n * 3 + 1];
    float p2 = g_pot3[(size_t)n * 3 + 2];
    out[(size_t)n * 40 + 0] += 0.1f * (p2 - p1);
    out[(size_t)n * 40 + 1] += 0.1f * (p0 - p2);
    out[(size_t)n * 40 + 2] += 0.1f * (p1 - p0);
}

extern "C" void kernel_launch(void* const* d_in, const int* in_sizes, int n_in,
                              void* d_out, int out_size) {
    const float* feats = (const float*)d_in[0];
    const float* pos   = (const float*)d_in[1];
    const int*   esrc  = (const int*)d_in[2];
    const int*   edst  = (const int*)d_in[3];
    const float* Wq0   = (const float*)d_in[4];
    const float* Wq1   = (const float*)d_in[5];
    const float* W1k   = (const float*)d_in[6];
    const float* W2k   = (const float*)d_in[7];
    const float* W1v   = (const float*)d_in[8];
    const float* W2v   = (const float*)d_in[9];
    const float* Wd00  = (const float*)d_in[10];
    const float* Wd11  = (const float*)d_in[11];
    const float* W1p   = (const float*)d_in[12];
    const float* W2p   = (const float*)d_in[13];
    float* out = (float*)d_out;

    const int smem_bytes = SMEM_FLOATS * 4;
    cudaFuncSetAttribute(kEdgeMain, cudaFuncAttributeMaxDynamicSharedMemorySize, smem_bytes);

    kInit<<<(NNODE * 40 + 255) / 256, 256>>>(out, W2k, W2v, feats, Wq0, Wq1, Wd00, Wd11);
    kEdgeMain<<<NEDGE / EPB, 256, smem_bytes>>>(feats, pos, esrc, edst,
                                                W1k, W1v, W1p, W2p);
    kAttScatter<<<(NEDGE * 40 + 255) / 256, 256>>>(edst, out);
    kPEdge<<<(NEDGE + 255) / 256, 256>>>(esrc, edst, out);
    kCurl<<<(NNODE + 255) / 256, 256>>>(out);
}